// round 6
// baseline (speedup 1.0000x reference)
#include <cuda_runtime.h>

// SVConv2d: out[n,o,h,w] = bias[o] + sum_{ci,kh,kw} x[n,ci,h+kh-1,w+kw-1] * W[o,ci,kh,kw,h,w]
// N=8, Cin=Cout=32, K=3, H=W=64. Weight (151 MB) streams once -> DRAM-bound.
// R6: no cin split, no reduce pass (direct out write + bias). cin loop
// unrolled x4 so weight loads from consecutive cins batch into one long
// LDG burst (hides DRAM latency). x stays in zero-padded (cin,66,66)
// float4 planes; barrier-free.

typedef unsigned long long ull;

#define HW 4096
#define PD 66            // padded spatial dim
#define PP (PD * PD)     // 4356
#define CPB 2

// scratch (allocation-free: __device__ globals)
__device__ float4 g_xp0[32 * PP];              // (cin, 66, 66) n0..3 : 2.2 MB
__device__ float4 g_xp1[32 * PP];              // (cin, 66, 66) n4..7 : 2.2 MB

__device__ __forceinline__ ull pack2(float a, float b) {
    ull r; asm("mov.b64 %0, {%1, %2};" : "=l"(r) : "f"(a), "f"(b)); return r;
}
__device__ __forceinline__ void fma2(ull& d, ull a, ull b) {
    asm("fma.rn.f32x2 %0, %1, %2, %0;" : "+l"(d) : "l"(a), "l"(b));
}
__device__ __forceinline__ float2 unpack2(ull v) {
    float x, y; asm("mov.b64 {%0, %1}, %2;" : "=f"(x), "=f"(y) : "l"(v));
    return make_float2(x, y);
}

// ---- kernel 1: build padded transposed x planes (border = 0) ----
__global__ __launch_bounds__(256) void build_xpad(const float* __restrict__ x) {
    int idx = blockIdx.x * 256 + threadIdx.x;       // < 32 * PP
    if (idx >= 32 * PP) return;
    int cin = idx / PP, rc = idx - cin * PP;
    int hp = rc / PD, wp = rc - hp * PD;            // padded coords
    float4 lo = make_float4(0.f, 0.f, 0.f, 0.f);
    float4 hi = lo;
    int h = hp - 1, w = wp - 1;
    if ((unsigned)h < 64u && (unsigned)w < 64u) {
        int pix = h * 64 + w;
        lo.x = x[(0 * 32 + cin) * HW + pix];
        lo.y = x[(1 * 32 + cin) * HW + pix];
        lo.z = x[(2 * 32 + cin) * HW + pix];
        lo.w = x[(3 * 32 + cin) * HW + pix];
        hi.x = x[(4 * 32 + cin) * HW + pix];
        hi.y = x[(5 * 32 + cin) * HW + pix];
        hi.z = x[(6 * 32 + cin) * HW + pix];
        hi.w = x[(7 * 32 + cin) * HW + pix];
    }
    g_xp0[idx] = lo;
    g_xp1[idx] = hi;
}

// ---- kernel 2: main. block (32,4); warp = 32 consecutive w; no smem/barriers ----
__global__ __launch_bounds__(128) void svconv_main(const float* __restrict__ wt_g,
                                                   const float* __restrict__ bias,
                                                   float* __restrict__ out) {
    const int lane = threadIdx.x, row = threadIdx.y;
    const int px = blockIdx.x * 32 + lane;
    const int py = blockIdx.y * 4 + row;
    const int c0 = blockIdx.z * CPB;               // cout group (2 couts)

    ull acc[CPB][4];
#pragma unroll
    for (int c = 0; c < CPB; c++)
#pragma unroll
        for (int j = 0; j < 4; j++) acc[c][j] = 0ull;

    // padded center pointers for this thread
    const float4* xb0 = g_xp0 + (py + 1) * PD + (px + 1);
    const float4* xb1 = g_xp1 + (py + 1) * PD + (px + 1);
    const float* wp = wt_g + (size_t)(c0 * 32) * 9 * HW + py * 64 + px;

#pragma unroll 4
    for (int ci = 0; ci < 32; ci++) {
#pragma unroll
        for (int t = 0; t < 9; t++) {
            const int off = (t / 3 - 1) * PD + (t % 3 - 1);  // compile-time
            float4 lo = __ldg(xb0 + off);
            float4 hi = __ldg(xb1 + off);
            float wv0 = __ldcs(wp + t * HW);
            float wv1 = __ldcs(wp + (size_t)(32 * 9) * HW + t * HW);
            ull xq0 = pack2(lo.x, lo.y);
            ull xq1 = pack2(lo.z, lo.w);
            ull xq2 = pack2(hi.x, hi.y);
            ull xq3 = pack2(hi.z, hi.w);
            ull wd0 = pack2(wv0, wv0);
            ull wd1 = pack2(wv1, wv1);
            fma2(acc[0][0], wd0, xq0);
            fma2(acc[0][1], wd0, xq1);
            fma2(acc[0][2], wd0, xq2);
            fma2(acc[0][3], wd0, xq3);
            fma2(acc[1][0], wd1, xq0);
            fma2(acc[1][1], wd1, xq1);
            fma2(acc[1][2], wd1, xq2);
            fma2(acc[1][3], wd1, xq3);
        }
        xb0 += PP;           // next cin
        xb1 += PP;
        wp += 9 * HW;
    }

    // ---- epilogue: bias + direct out write, coalesced along w ----
    const int pix = py * 64 + px;
#pragma unroll
    for (int c = 0; c < CPB; c++) {
        float b = __ldg(bias + c0 + c);
#pragma unroll
        for (int j = 0; j < 4; j++) {
            float2 v = unpack2(acc[c][j]);
            int n0 = 2 * j, n1 = 2 * j + 1;
            out[((size_t)(n0 * 32) + c0 + c) * HW + pix] = v.x + b;
            out[((size_t)(n1 * 32) + c0 + c) * HW + pix] = v.y + b;
        }
    }
}

extern "C" void kernel_launch(void* const* d_in, const int* in_sizes, int n_in,
                              void* d_out, int out_size) {
    const float* x = (const float*)d_in[0];
    const float* wgt = (const float*)d_in[1];
    const float* bias = (const float*)d_in[2];
    float* out = (float*)d_out;

    build_xpad<<<(32 * PP + 255) / 256, 256>>>(x);
    dim3 grid(2, 16, 32 / CPB);                    // 2 x 16 x 16 = 512 blocks
    dim3 block(32, 4);                             // 128 threads
    svconv_main<<<grid, block>>>(wgt, bias, out);
}

// round 8
// speedup vs baseline: 1.9403x; 1.9403x over previous
#include <cuda_runtime.h>

// SVConv2d: out[n,o,h,w] = bias[o] + sum_{ci,kh,kw} x[n,ci,h+kh-1,w+kw-1] * W[o,ci,kh,kw,h,w]
// N=8, Cin=Cout=32, K=3, H=W=64. Weight (151 MB) streams once -> DRAM-bound.
// R8: R7 with the prefetch-offset bug fixed (2 cins ahead = 2*9*HW, not 18*9*HW).
// Double-buffered weight prefetch (wA/wB, 18 regs each) keeps >=18 weight
// lines in flight per warp. SPLIT=2, CPB=2, 1024 blocks, padded x planes,
// barrier-free.

typedef unsigned long long ull;

#define HW 4096
#define PD 66            // padded spatial dim
#define PP (PD * PD)     // 4356
#define SPLIT 2
#define CPB 2

// scratch (allocation-free: __device__ globals)
__device__ float4 g_xp0[32 * PP];              // (cin, 66, 66) n0..3 : 2.2 MB
__device__ float4 g_xp1[32 * PP];              // (cin, 66, 66) n4..7 : 2.2 MB
__device__ float g_part[SPLIT * 8 * 32 * HW];  // partial sums : 8 MB

__device__ __forceinline__ ull pack2(float a, float b) {
    ull r; asm("mov.b64 %0, {%1, %2};" : "=l"(r) : "f"(a), "f"(b)); return r;
}
__device__ __forceinline__ void fma2(ull& d, ull a, ull b) {
    asm("fma.rn.f32x2 %0, %1, %2, %0;" : "+l"(d) : "l"(a), "l"(b));
}
__device__ __forceinline__ float2 unpack2(ull v) {
    float x, y; asm("mov.b64 {%0, %1}, %2;" : "=f"(x), "=f"(y) : "l"(v));
    return make_float2(x, y);
}

// ---- kernel 1: build padded transposed x planes (border = 0) ----
__global__ __launch_bounds__(256) void build_xpad(const float* __restrict__ x) {
    int idx = blockIdx.x * 256 + threadIdx.x;       // < 32 * PP
    if (idx >= 32 * PP) return;
    int cin = idx / PP, rc = idx - cin * PP;
    int hp = rc / PD, wp = rc - hp * PD;            // padded coords
    float4 lo = make_float4(0.f, 0.f, 0.f, 0.f);
    float4 hi = lo;
    int h = hp - 1, w = wp - 1;
    if ((unsigned)h < 64u && (unsigned)w < 64u) {
        int pix = h * 64 + w;
        lo.x = x[(0 * 32 + cin) * HW + pix];
        lo.y = x[(1 * 32 + cin) * HW + pix];
        lo.z = x[(2 * 32 + cin) * HW + pix];
        lo.w = x[(3 * 32 + cin) * HW + pix];
        hi.x = x[(4 * 32 + cin) * HW + pix];
        hi.y = x[(5 * 32 + cin) * HW + pix];
        hi.z = x[(6 * 32 + cin) * HW + pix];
        hi.w = x[(7 * 32 + cin) * HW + pix];
    }
    g_xp0[idx] = lo;
    g_xp1[idx] = hi;
}

// load 18 weights (9 taps x 2 couts) for one cin into registers
__device__ __forceinline__ void loadW(float* wb, const float* wp) {
#pragma unroll
    for (int t = 0; t < 9; t++) {
        wb[t] = __ldcs(wp + t * HW);
        wb[9 + t] = __ldcs(wp + (size_t)(32 * 9) * HW + t * HW);
    }
}

// consume one cin: 18 x-load quads worth of FMAs with registered weights
__device__ __forceinline__ void fmaTaps(const float* wb,
                                        const float4* xb0, const float4* xb1,
                                        ull acc[CPB][4]) {
#pragma unroll
    for (int t = 0; t < 9; t++) {
        const int off = (t / 3 - 1) * PD + (t % 3 - 1);  // compile-time
        float4 lo = __ldg(xb0 + off);
        float4 hi = __ldg(xb1 + off);
        ull xq0 = pack2(lo.x, lo.y);
        ull xq1 = pack2(lo.z, lo.w);
        ull xq2 = pack2(hi.x, hi.y);
        ull xq3 = pack2(hi.z, hi.w);
        ull wd0 = pack2(wb[t], wb[t]);
        ull wd1 = pack2(wb[9 + t], wb[9 + t]);
        fma2(acc[0][0], wd0, xq0);
        fma2(acc[0][1], wd0, xq1);
        fma2(acc[0][2], wd0, xq2);
        fma2(acc[0][3], wd0, xq3);
        fma2(acc[1][0], wd1, xq0);
        fma2(acc[1][1], wd1, xq1);
        fma2(acc[1][2], wd1, xq2);
        fma2(acc[1][3], wd1, xq3);
    }
}

// ---- kernel 2: main. block (32,4); warp = 32 consecutive w; no smem/barriers ----
__global__ __launch_bounds__(128) void svconv_main(const float* __restrict__ wt_g) {
    const int lane = threadIdx.x, row = threadIdx.y;
    const int px = blockIdx.x * 32 + lane;
    const int py = blockIdx.y * 4 + row;
    const int c0 = (blockIdx.z & 15) * CPB;        // cout group (2 couts)
    const int s = blockIdx.z >> 4;                 // cin half

    ull acc[CPB][4];
#pragma unroll
    for (int c = 0; c < CPB; c++)
#pragma unroll
        for (int j = 0; j < 4; j++) acc[c][j] = 0ull;

    const float4* xb0 = g_xp0 + (size_t)(s * 16) * PP + (py + 1) * PD + (px + 1);
    const float4* xb1 = g_xp1 + (size_t)(s * 16) * PP + (py + 1) * PD + (px + 1);
    const float* wp = wt_g + (size_t)(c0 * 32 + s * 16) * 9 * HW + py * 64 + px;

    float wA[18], wB[18];
    loadW(wA, wp);                                  // cin 0

#pragma unroll 1
    for (int ci = 0; ci < 16; ci += 2) {
        // prefetch cin+1 while consuming cin (ci+1 <= 15 always valid)
        loadW(wB, wp + (size_t)9 * HW);
        fmaTaps(wA, xb0, xb1, acc);
        xb0 += PP; xb1 += PP;

        // prefetch cin+2 while consuming cin+1 (clamp last to stay in-bounds)
        const float* p2 = wp + (size_t)(ci + 2 < 16 ? 2 : 0) * 9 * HW;
        loadW(wA, p2);
        fmaTaps(wB, xb0, xb1, acc);
        xb0 += PP; xb1 += PP;

        wp += (size_t)18 * HW;                     // advance 2 cins (2*9*HW)
    }

    // write partials (no bias here), coalesced along w
    float* pb = g_part + (size_t)s * (8 * 32 * HW) + (size_t)c0 * HW + py * 64 + px;
#pragma unroll
    for (int c = 0; c < CPB; c++)
#pragma unroll
        for (int j = 0; j < 4; j++) {
            float2 v = unpack2(acc[c][j]);
            int n0 = 2 * j, n1 = 2 * j + 1;
            pb[(((size_t)n0 * 32) + c) * HW] = v.x;
            pb[(((size_t)n1 * 32) + c) * HW] = v.y;
        }
}

// ---- kernel 3: reduce partials + bias ----
__global__ __launch_bounds__(256) void reduce_out(const float* __restrict__ bias,
                                                  float* __restrict__ out) {
    int idx = blockIdx.x * 256 + threadIdx.x;      // < 8*32*4096
    int o = (idx >> 12) & 31;
    out[idx] = g_part[idx] + g_part[idx + 8 * 32 * HW] + bias[o];
}

extern "C" void kernel_launch(void* const* d_in, const int* in_sizes, int n_in,
                              void* d_out, int out_size) {
    const float* x = (const float*)d_in[0];
    const float* wgt = (const float*)d_in[1];
    const float* bias = (const float*)d_in[2];
    float* out = (float*)d_out;

    build_xpad<<<(32 * PP + 255) / 256, 256>>>(x);
    dim3 grid(2, 16, 16 * SPLIT);                  // 1024 blocks
    dim3 block(32, 4);                             // 128 threads
    svconv_main<<<grid, block>>>(wgt);
    reduce_out<<<(8 * 32 * HW) / 256, 256>>>(bias, out);
}